// round 2
// baseline (speedup 1.0000x reference)
#include <cuda_runtime.h>
#include <math.h>

// Problem constants (fixed by the reference)
#define NN 50000
#define NE 800000
#define INC 128
#define OUTC 64
#define HEADS 4
#define HC (HEADS * OUTC)   // 256
#define NEG_SLOPE 0.2f
#define ET (NE + NN)        // edges + self-loops

// ---------------- scratch (device globals; no allocation allowed) ----------
__device__ float g_h[(size_t)NN * HC];              // projected features [N,256]
__device__ float g_asrc[NN * HEADS];                // per-node att halves
__device__ float g_adst[NN * HEADS];
__device__ float g_m[NN * HEADS];                   // segment max
__device__ float g_den[NN * HEADS];                 // segment sum
__device__ float g_s[(size_t)ET * HEADS];           // per-edge scores / exp
__device__ int   g_is64;                            // edge_index dtype flag

// ---------------- helpers ---------------------------------------------------
__device__ __forceinline__ void atomicMaxF(float* addr, float val) {
    if (val >= 0.0f)
        atomicMax((int*)addr, __float_as_int(val));
    else
        atomicMin((unsigned int*)addr, __float_as_uint(val));
}

__device__ __forceinline__ float lrelu(float v) {
    return v >= 0.0f ? v : NEG_SLOPE * v;
}

// Load one edge endpoint, robust to int32 vs int64 storage.
__device__ __forceinline__ int edge_at(const void* ei, long long idx) {
    if (g_is64) return (int)((const long long*)ei)[idx];
    return ((const int*)ei)[idx];
}

// ---------------- 0) dtype detection ----------------------------------------
// int64 little-endian values in [0,50000) => every odd 32-bit word is 0.
// int32 node ids => odd words are actual ids, essentially never all zero.
__global__ void detect_kernel(const int* __restrict__ ei_raw) {
    __shared__ int nz;
    if (threadIdx.x == 0) nz = 0;
    __syncthreads();
    int local = 0;
    for (int i = threadIdx.x; i < 4096; i += blockDim.x)
        if (ei_raw[2 * i + 1] != 0) local = 1;
    if (local) atomicOr(&nz, 1);
    __syncthreads();
    if (threadIdx.x == 0) g_is64 = (nz == 0) ? 1 : 0;
}

// ---------------- 1) SGEMM: h[N,256] = x[N,128] @ W[256,128]^T --------------
__global__ __launch_bounds__(256) void gemm_kernel(
    const float* __restrict__ x, const float* __restrict__ W)
{
    __shared__ float xs[32][64];    // [k][row]
    __shared__ float ws[32][256];   // [k][col]

    const int tid = threadIdx.x;
    const int tx = tid & 15;
    const int ty = tid >> 4;
    const int rowBase = blockIdx.x * 64;

    float acc[4][16];
#pragma unroll
    for (int r = 0; r < 4; r++)
#pragma unroll
        for (int c = 0; c < 16; c++) acc[r][c] = 0.0f;

    for (int k0 = 0; k0 < INC; k0 += 32) {
#pragma unroll
        for (int i = 0; i < 2; i++) {
            int t = tid + i * 256;
            int r = t >> 3;
            int kk = (t & 7) * 4;
            float4 v = make_float4(0.f, 0.f, 0.f, 0.f);
            int gr = rowBase + r;
            if (gr < NN) v = *(const float4*)&x[(size_t)gr * INC + k0 + kk];
            xs[kk + 0][r] = v.x; xs[kk + 1][r] = v.y;
            xs[kk + 2][r] = v.z; xs[kk + 3][r] = v.w;
        }
#pragma unroll
        for (int i = 0; i < 8; i++) {
            int t = tid + i * 256;
            int c = t >> 3;
            int kk = (t & 7) * 4;
            float4 v = *(const float4*)&W[(size_t)c * INC + k0 + kk];
            ws[kk + 0][c] = v.x; ws[kk + 1][c] = v.y;
            ws[kk + 2][c] = v.z; ws[kk + 3][c] = v.w;
        }
        __syncthreads();

#pragma unroll
        for (int k = 0; k < 32; k++) {
            float4 xf = *(const float4*)&xs[k][ty * 4];
            float wf[16];
            *(float4*)&wf[0]  = *(const float4*)&ws[k][tx * 16 + 0];
            *(float4*)&wf[4]  = *(const float4*)&ws[k][tx * 16 + 4];
            *(float4*)&wf[8]  = *(const float4*)&ws[k][tx * 16 + 8];
            *(float4*)&wf[12] = *(const float4*)&ws[k][tx * 16 + 12];
            float xv[4] = {xf.x, xf.y, xf.z, xf.w};
#pragma unroll
            for (int r = 0; r < 4; r++)
#pragma unroll
                for (int c = 0; c < 16; c++)
                    acc[r][c] = fmaf(xv[r], wf[c], acc[r][c]);
        }
        __syncthreads();
    }

#pragma unroll
    for (int r = 0; r < 4; r++) {
        int gr = rowBase + ty * 4 + r;
        if (gr >= NN) continue;
        float* hp = &g_h[(size_t)gr * HC + tx * 16];
#pragma unroll
        for (int q = 0; q < 4; q++)
            *(float4*)&hp[q * 4] = *(float4*)&acc[r][q * 4];
    }
}

// ---------------- 2) per-node attention halves ------------------------------
__global__ __launch_bounds__(256) void att_kernel(
    const float* __restrict__ att_src, const float* __restrict__ att_dst)
{
    int gtid = blockIdx.x * blockDim.x + threadIdx.x;
    int node = gtid >> 5;
    int lane = threadIdx.x & 31;
    if (node >= NN) return;

    int head = lane >> 3;
    int off = (lane & 7) * 8;
    const float* hp = &g_h[(size_t)node * HC + head * OUTC + off];
    const float* as = &att_src[head * OUTC + off];
    const float* ad = &att_dst[head * OUTC + off];

    float4 h0 = *(const float4*)&hp[0];
    float4 h1 = *(const float4*)&hp[4];
    float4 a0 = *(const float4*)&as[0];
    float4 a1 = *(const float4*)&as[4];
    float4 b0 = *(const float4*)&ad[0];
    float4 b1 = *(const float4*)&ad[4];
    float s = h0.x*a0.x + h0.y*a0.y + h0.z*a0.z + h0.w*a0.w
            + h1.x*a1.x + h1.y*a1.y + h1.z*a1.z + h1.w*a1.w;
    float d = h0.x*b0.x + h0.y*b0.y + h0.z*b0.z + h0.w*b0.w
            + h1.x*b1.x + h1.y*b1.y + h1.z*b1.z + h1.w*b1.w;

#pragma unroll
    for (int sh = 4; sh >= 1; sh >>= 1) {
        s += __shfl_down_sync(0xffffffffu, s, sh, 8);
        d += __shfl_down_sync(0xffffffffu, d, sh, 8);
    }
    if ((lane & 7) == 0) {
        g_asrc[node * HEADS + head] = s;
        g_adst[node * HEADS + head] = d;
    }
}

// ---------------- 3) init ---------------------------------------------------
__global__ void init_kernel(float* __restrict__ out)
{
    int i = blockIdx.x * blockDim.x + threadIdx.x;
    if (i < NN * OUTC) out[i] = 0.0f;
    if (i < NN * HEADS) {
        g_m[i] = -INFINITY;
        g_den[i] = 0.0f;
    }
}

// ---------------- 4) edge pass A: score + segment max -----------------------
__global__ void edge_max_kernel(const void* __restrict__ ei)
{
    int e = blockIdx.x * blockDim.x + threadIdx.x;
    if (e >= ET) return;
    int src, dst;
    if (e < NE) {
        src = edge_at(ei, e);
        dst = edge_at(ei, (long long)NE + e);
    } else {
        src = dst = e - NE;
    }
    float4 as = *(const float4*)&g_asrc[src * HEADS];
    float4 ad = *(const float4*)&g_adst[dst * HEADS];
    float4 s;
    s.x = lrelu(as.x + ad.x);
    s.y = lrelu(as.y + ad.y);
    s.z = lrelu(as.z + ad.z);
    s.w = lrelu(as.w + ad.w);
    *(float4*)&g_s[(size_t)e * HEADS] = s;
    float* mp = &g_m[dst * HEADS];
    atomicMaxF(&mp[0], s.x);
    atomicMaxF(&mp[1], s.y);
    atomicMaxF(&mp[2], s.z);
    atomicMaxF(&mp[3], s.w);
}

// ---------------- 5) edge pass B: exp + segment sum --------------------------
__global__ void edge_exp_kernel(const void* __restrict__ ei)
{
    int e = blockIdx.x * blockDim.x + threadIdx.x;
    if (e >= ET) return;
    int dst;
    if (e < NE) dst = edge_at(ei, (long long)NE + e);
    else dst = e - NE;

    float4 s = *(const float4*)&g_s[(size_t)e * HEADS];
    float4 m = *(const float4*)&g_m[dst * HEADS];
    float4 ex;
    ex.x = __expf(s.x - m.x);
    ex.y = __expf(s.y - m.y);
    ex.z = __expf(s.z - m.z);
    ex.w = __expf(s.w - m.w);
    *(float4*)&g_s[(size_t)e * HEADS] = ex;
    float* dp = &g_den[dst * HEADS];
    atomicAdd(&dp[0], ex.x);
    atomicAdd(&dp[1], ex.y);
    atomicAdd(&dp[2], ex.z);
    atomicAdd(&dp[3], ex.w);
}

// ---------------- 6) edge pass C: weighted scatter (head-mean folded) -------
__global__ __launch_bounds__(256) void scatter_kernel(
    const void* __restrict__ ei, float* __restrict__ out)
{
    int gtid = blockIdx.x * blockDim.x + threadIdx.x;
    int e = gtid >> 5;
    int lane = threadIdx.x & 31;
    if (e >= ET) return;
    int src, dst;
    if (e < NE) {
        src = edge_at(ei, e);
        dst = edge_at(ei, (long long)NE + e);
    } else {
        src = dst = e - NE;
    }
    float4 ex = *(const float4*)&g_s[(size_t)e * HEADS];
    float4 dn = *(const float4*)&g_den[dst * HEADS];
    float a0 = 0.25f * ex.x / dn.x;
    float a1 = 0.25f * ex.y / dn.y;
    float a2 = 0.25f * ex.z / dn.z;
    float a3 = 0.25f * ex.w / dn.w;

    const float* hp = &g_h[(size_t)src * HC];
    float* op = &out[(size_t)dst * OUTC];
#pragma unroll
    for (int half = 0; half < 2; half++) {
        int c = lane + half * 32;
        float v = a0 * hp[c]
                + a1 * hp[64 + c]
                + a2 * hp[128 + c]
                + a3 * hp[192 + c];
        atomicAdd(&op[c], v);
    }
}

// ---------------- 7) finalize: bias + ReLU in place --------------------------
__global__ void final_kernel(float* __restrict__ out, const float* __restrict__ bias)
{
    int i = blockIdx.x * blockDim.x + threadIdx.x;
    if (i >= NN * OUTC) return;
    float v = out[i] + bias[i & (OUTC - 1)];
    out[i] = fmaxf(v, 0.0f);
}

// ---------------- launch -----------------------------------------------------
extern "C" void kernel_launch(void* const* d_in, const int* in_sizes, int n_in,
                              void* d_out, int out_size)
{
    const float* x       = (const float*)d_in[0];
    const void*  ei      = d_in[1];
    const float* W       = (const float*)d_in[2];
    const float* att_src = (const float*)d_in[3];
    const float* att_dst = (const float*)d_in[4];
    const float* bias    = (const float*)d_in[5];
    float* out = (float*)d_out;

    // 0) edge dtype detection (one block)
    detect_kernel<<<1, 256>>>((const int*)ei);
    // 1) projection GEMM
    gemm_kernel<<<(NN + 63) / 64, 256>>>(x, W);
    // 2) per-node attention halves
    att_kernel<<<(NN * 32 + 255) / 256, 256>>>(att_src, att_dst);
    // 3) init accumulators + output
    init_kernel<<<(NN * OUTC + 255) / 256, 256>>>(out);
    // 4) edge score + segment max
    edge_max_kernel<<<(ET + 255) / 256, 256>>>(ei);
    // 5) edge exp + segment sum
    edge_exp_kernel<<<(ET + 255) / 256, 256>>>(ei);
    // 6) weighted scatter-sum (one warp per edge)
    scatter_kernel<<<((size_t)ET * 32 + 255) / 256, 256>>>(ei, out);
    // 7) bias + ReLU
    final_kernel<<<(NN * OUTC + 255) / 256, 256>>>(out, bias);
}

// round 3
// speedup vs baseline: 1.2492x; 1.2492x over previous
#include <cuda_runtime.h>
#include <math.h>

// Problem constants (fixed by the reference)
#define NN 50000
#define NE 800000
#define INC 128
#define OUTC 64
#define HEADS 4
#define HC (HEADS * OUTC)   // 256
#define NEG_SLOPE 0.2f
#define ET (NE + NN)        // edges + self-loops

// ---------------- scratch (device globals) -----------------------------------
__device__ float g_h[(size_t)NN * HC];      // projected features [N,256]
__device__ float g_asrc[NN * HEADS];        // per-node att halves
__device__ float g_adst[NN * HEADS];
__device__ float g_den[NN * HEADS];         // segment sum of exp
__device__ float g_s[(size_t)ET * HEADS];   // per-edge exp(score)
__device__ int   g_is64;                    // edge_index dtype flag

// ---------------- helpers -----------------------------------------------------
__device__ __forceinline__ float lrelu(float v) {
    return v >= 0.0f ? v : NEG_SLOPE * v;
}

__device__ __forceinline__ int edge_at(const void* ei, long long idx) {
    if (g_is64) return (int)((const long long*)ei)[idx];
    return ((const int*)ei)[idx];
}

__device__ __forceinline__ unsigned long long pack2(float lo, float hi) {
    unsigned long long r;
    asm("mov.b64 %0, {%1, %2};" : "=l"(r) : "f"(lo), "f"(hi));
    return r;
}
__device__ __forceinline__ void unpack2(unsigned long long v, float& lo, float& hi) {
    asm("mov.b64 {%0, %1}, %2;" : "=f"(lo), "=f"(hi) : "l"(v));
}
__device__ __forceinline__ unsigned long long fma2(
    unsigned long long a, unsigned long long b, unsigned long long c) {
    unsigned long long d;
    asm("fma.rn.f32x2 %0, %1, %2, %3;" : "=l"(d) : "l"(a), "l"(b), "l"(c));
    return d;
}

__device__ __forceinline__ void red_add_v4(float* addr, float4 v) {
    asm volatile("red.global.add.v4.f32 [%0], {%1, %2, %3, %4};"
                 :: "l"(addr), "f"(v.x), "f"(v.y), "f"(v.z), "f"(v.w)
                 : "memory");
}

// ---------------- 0) dtype detection ------------------------------------------
__global__ void detect_kernel(const int* __restrict__ ei_raw) {
    __shared__ int nz;
    if (threadIdx.x == 0) nz = 0;
    __syncthreads();
    int local = 0;
    for (int i = threadIdx.x; i < 4096; i += blockDim.x)
        if (ei_raw[2 * i + 1] != 0) local = 1;
    if (local) atomicOr(&nz, 1);
    __syncthreads();
    if (threadIdx.x == 0) g_is64 = (nz == 0) ? 1 : 0;
}

// ---------------- 1) SGEMM + fused attention halves ---------------------------
// h[N,256] = x[N,128] @ W[256,128]^T, then a_src/a_dst per node/head.
// CTA: 64 rows x 256 cols, 256 threads, 4x16 microtile, f32x2 packed FMA.
__global__ __launch_bounds__(256) void gemm_kernel(
    const float* __restrict__ x, const float* __restrict__ W,
    const float* __restrict__ att_src, const float* __restrict__ att_dst)
{
    __shared__ float xs[32][64];    // [k][row]
    __shared__ float ws[32][256];   // [k][col]

    const int tid = threadIdx.x;
    const int tx = tid & 15;
    const int ty = tid >> 4;
    const int lane = tid & 31;
    const int rowBase = blockIdx.x * 64;

    unsigned long long acc2[4][8];  // packed pairs: cols tx*16 + 2c .. +1
#pragma unroll
    for (int r = 0; r < 4; r++)
#pragma unroll
        for (int c = 0; c < 8; c++) acc2[r][c] = 0ull;

    for (int k0 = 0; k0 < INC; k0 += 32) {
#pragma unroll
        for (int i = 0; i < 2; i++) {
            int t = tid + i * 256;
            int r = t >> 3;
            int kk = (t & 7) * 4;
            float4 v = make_float4(0.f, 0.f, 0.f, 0.f);
            int gr = rowBase + r;
            if (gr < NN) v = *(const float4*)&x[(size_t)gr * INC + k0 + kk];
            xs[kk + 0][r] = v.x; xs[kk + 1][r] = v.y;
            xs[kk + 2][r] = v.z; xs[kk + 3][r] = v.w;
        }
#pragma unroll
        for (int i = 0; i < 8; i++) {
            int t = tid + i * 256;
            int c = t >> 3;
            int kk = (t & 7) * 4;
            float4 v = *(const float4*)&W[(size_t)c * INC + k0 + kk];
            ws[kk + 0][c] = v.x; ws[kk + 1][c] = v.y;
            ws[kk + 2][c] = v.z; ws[kk + 3][c] = v.w;
        }
        __syncthreads();

#pragma unroll
        for (int k = 0; k < 32; k++) {
            float4 xf = *(const float4*)&xs[k][ty * 4];
            unsigned long long xp[4];
            xp[0] = pack2(xf.x, xf.x);
            xp[1] = pack2(xf.y, xf.y);
            xp[2] = pack2(xf.z, xf.z);
            xp[3] = pack2(xf.w, xf.w);
            const ulonglong2* wrow = (const ulonglong2*)&ws[k][tx * 16];
#pragma unroll
            for (int q = 0; q < 4; q++) {
                ulonglong2 wv = wrow[q];
#pragma unroll
                for (int r = 0; r < 4; r++) {
                    acc2[r][2 * q + 0] = fma2(xp[r], wv.x, acc2[r][2 * q + 0]);
                    acc2[r][2 * q + 1] = fma2(xp[r], wv.y, acc2[r][2 * q + 1]);
                }
            }
        }
        __syncthreads();
    }

    // unpack accumulators
    float acc[4][16];
#pragma unroll
    for (int r = 0; r < 4; r++)
#pragma unroll
        for (int c = 0; c < 8; c++)
            unpack2(acc2[r][c], acc[r][2 * c], acc[r][2 * c + 1]);

    // store h
#pragma unroll
    for (int r = 0; r < 4; r++) {
        int gr = rowBase + ty * 4 + r;
        if (gr >= NN) continue;
        float* hp = &g_h[(size_t)gr * HC + tx * 16];
#pragma unroll
        for (int q = 0; q < 4; q++)
            *(float4*)&hp[q * 4] = *(float4*)&acc[r][q * 4];
    }

    // fused attention halves: this thread's 16 cols live in head = tx>>2
    const int head = tx >> 2;
    const int off = (tx & 3) * 16;
    float av[16], bv[16];
#pragma unroll
    for (int q = 0; q < 4; q++) {
        *(float4*)&av[q * 4] = *(const float4*)&att_src[head * OUTC + off + q * 4];
        *(float4*)&bv[q * 4] = *(const float4*)&att_dst[head * OUTC + off + q * 4];
    }
#pragma unroll
    for (int r = 0; r < 4; r++) {
        float s = 0.0f, d = 0.0f;
#pragma unroll
        for (int q = 0; q < 16; q++) {
            s = fmaf(acc[r][q], av[q], s);
            d = fmaf(acc[r][q], bv[q], d);
        }
        // reduce over the 4-lane group (same ty, same head)
        s += __shfl_xor_sync(0xffffffffu, s, 1);
        s += __shfl_xor_sync(0xffffffffu, s, 2);
        d += __shfl_xor_sync(0xffffffffu, d, 1);
        d += __shfl_xor_sync(0xffffffffu, d, 2);
        int gr = rowBase + ty * 4 + r;
        if ((lane & 3) == 0 && gr < NN) {
            g_asrc[gr * HEADS + head] = s;
            g_adst[gr * HEADS + head] = d;
        }
    }
}

// ---------------- 2) init ------------------------------------------------------
__global__ void init_kernel(float* __restrict__ out)
{
    int i = blockIdx.x * blockDim.x + threadIdx.x;
    if (i < NN * OUTC) out[i] = 0.0f;
    if (i < NN * HEADS) g_den[i] = 0.0f;
}

// ---------------- 3) edge pass: score + exp + segment sum (no max) ------------
__global__ void edge_kernel(const void* __restrict__ ei)
{
    int e = blockIdx.x * blockDim.x + threadIdx.x;
    if (e >= ET) return;
    int src, dst;
    if (e < NE) {
        src = edge_at(ei, e);
        dst = edge_at(ei, (long long)NE + e);
    } else {
        src = dst = e - NE;
    }
    float4 as = *(const float4*)&g_asrc[src * HEADS];
    float4 ad = *(const float4*)&g_adst[dst * HEADS];
    float4 ex;
    ex.x = __expf(lrelu(as.x + ad.x));
    ex.y = __expf(lrelu(as.y + ad.y));
    ex.z = __expf(lrelu(as.z + ad.z));
    ex.w = __expf(lrelu(as.w + ad.w));
    *(float4*)&g_s[(size_t)e * HEADS] = ex;
    red_add_v4(&g_den[dst * HEADS], ex);
}

// ---------------- 4) weighted scatter (head-mean folded, vector RED) ----------
// half-warp per edge; lane j in 0..15 handles channels 4j..4j+3
__global__ __launch_bounds__(256) void scatter_kernel(
    const void* __restrict__ ei, float* __restrict__ out)
{
    int gtid = blockIdx.x * blockDim.x + threadIdx.x;
    int e = (gtid >> 5) * 2 + ((gtid & 31) >> 4);
    int j = gtid & 15;
    if (e >= ET) return;
    int src, dst;
    if (e < NE) {
        src = edge_at(ei, e);
        dst = edge_at(ei, (long long)NE + e);
    } else {
        src = dst = e - NE;
    }
    float4 ex = *(const float4*)&g_s[(size_t)e * HEADS];
    float4 dn = *(const float4*)&g_den[dst * HEADS];
    float a0 = 0.25f * ex.x / dn.x;
    float a1 = 0.25f * ex.y / dn.y;
    float a2 = 0.25f * ex.z / dn.z;
    float a3 = 0.25f * ex.w / dn.w;

    const float4* hp = (const float4*)&g_h[(size_t)src * HC];
    float4 h0 = hp[j];
    float4 h1 = hp[16 + j];
    float4 h2 = hp[32 + j];
    float4 h3 = hp[48 + j];
    float4 v;
    v.x = a0 * h0.x + a1 * h1.x + a2 * h2.x + a3 * h3.x;
    v.y = a0 * h0.y + a1 * h1.y + a2 * h2.y + a3 * h3.y;
    v.z = a0 * h0.z + a1 * h1.z + a2 * h2.z + a3 * h3.z;
    v.w = a0 * h0.w + a1 * h1.w + a2 * h2.w + a3 * h3.w;
    red_add_v4(&out[(size_t)dst * OUTC + 4 * j], v);
}

// ---------------- 5) finalize: bias + ReLU in place ----------------------------
__global__ void final_kernel(float* __restrict__ out, const float* __restrict__ bias)
{
    int i = blockIdx.x * blockDim.x + threadIdx.x;
    if (i >= NN * OUTC) return;
    float v = out[i] + bias[i & (OUTC - 1)];
    out[i] = fmaxf(v, 0.0f);
}

// ---------------- launch --------------------------------------------------------
extern "C" void kernel_launch(void* const* d_in, const int* in_sizes, int n_in,
                              void* d_out, int out_size)
{
    const float* x       = (const float*)d_in[0];
    const void*  ei      = d_in[1];
    const float* W       = (const float*)d_in[2];
    const float* att_src = (const float*)d_in[3];
    const float* att_dst = (const float*)d_in[4];
    const float* bias    = (const float*)d_in[5];
    float* out = (float*)d_out;

    detect_kernel<<<1, 256>>>((const int*)ei);
    gemm_kernel<<<(NN + 63) / 64, 256>>>(x, W, att_src, att_dst);
    init_kernel<<<(NN * OUTC + 255) / 256, 256>>>(out);
    edge_kernel<<<(ET + 255) / 256, 256>>>(ei);
    scatter_kernel<<<((size_t)ET * 16 + 255) / 256, 256>>>(ei, out);
    final_kernel<<<(NN * OUTC + 255) / 256, 256>>>(out, bias);
}